// round 1
// baseline (speedup 1.0000x reference)
#include <cuda_runtime.h>

// Problem constants (fixed shapes from reference setup_inputs)
#define NPTS    2048          // points per cloud
#define UPR     10            // up ratio
#define QTOT    (NPTS*UPR + NPTS)   // 22528 query points
#define KNN     5
#define THREADS 256
#define SPLIT   4             // threads cooperating per query
#define QPB     (THREADS/SPLIT)     // 64 queries per block
#define NBLOCKS (QTOT/QPB)          // 352
#define EPS_D   1e-8f
#define EPS_N   1e-10f
#define BETA    3.0f

__device__ float g_partial[NBLOCKS];

// Insert (d, j) into sorted-ascending top-5 kept in registers (constant indices).
__device__ __forceinline__ void ins5(float d, int j, float dd[KNN], int ii[KNN]) {
    if (d < dd[4]) {
        dd[4] = d; ii[4] = j;
        if (dd[4] < dd[3]) { float t=dd[3]; dd[3]=dd[4]; dd[4]=t; int u=ii[3]; ii[3]=ii[4]; ii[4]=u; }
        if (dd[3] < dd[2]) { float t=dd[2]; dd[2]=dd[3]; dd[3]=t; int u=ii[2]; ii[2]=ii[3]; ii[3]=u; }
        if (dd[2] < dd[1]) { float t=dd[1]; dd[1]=dd[2]; dd[2]=t; int u=ii[1]; ii[1]=ii[2]; ii[2]=u; }
        if (dd[1] < dd[0]) { float t=dd[0]; dd[0]=dd[1]; dd[1]=t; int u=ii[0]; ii[0]=ii[1]; ii[1]=u; }
    }
}

// Merge partner's (snapshotted) top-5 into mine.
__device__ __forceinline__ void merge5(int xorMask, float dd[KNN], int ii[KNN]) {
    float od[KNN]; int oi[KNN];
#pragma unroll
    for (int r = 0; r < KNN; ++r) {
        od[r] = __shfl_xor_sync(0xFFFFFFFFu, dd[r], xorMask);
        oi[r] = __shfl_xor_sync(0xFFFFFFFFu, ii[r], xorMask);
    }
#pragma unroll
    for (int r = 0; r < KNN; ++r) ins5(od[r], oi[r], dd, ii);
}

// Weighted UDF gradient + UDF value from top-5 squared distances & indices.
__device__ __forceinline__ void udf_from_knn(
    float qx, float qy, float qz,
    const float dd[KNN], const int ii[KNN], const float* __restrict__ spts,
    float& gx, float& gy, float& gz, float& u)
{
    float inv[KNN];
    float ws = 0.f;
#pragma unroll
    for (int k = 0; k < KNN; ++k) { inv[k] = 1.0f / (dd[k] + EPS_D); ws += inv[k]; }
    float r = 1.0f / ws;
    gx = 0.f; gy = 0.f; gz = 0.f;
#pragma unroll
    for (int k = 0; k < KNN; ++k) {
        int b = 3 * ii[k];
        float w = inv[k] * r;
        gx = fmaf(qx - spts[b + 0], w, gx);
        gy = fmaf(qy - spts[b + 1], w, gy);
        gz = fmaf(qz - spts[b + 2], w, gz);
    }
    float ax = gx + EPS_N, ay = gy + EPS_N, az = gz + EPS_N;
    u = sqrtf(fmaf(ax, ax, fmaf(ay, ay, az * az)));
}

__global__ __launch_bounds__(THREADS)
void dirdist_kernel(const float* __restrict__ src,
                    const float* __restrict__ tgt,
                    const float* __restrict__ noise)
{
    __shared__ float s_tgt[NPTS * 3];   // 24 KB
    __shared__ float s_src[NPTS * 3];   // 24 KB  (total 48 KB; reused for reduction)

    const int tid = threadIdx.x;

    // Cooperative load of both clouds (float4-vectorized; 6144 floats each).
    {
        const float4* t4 = (const float4*)tgt;
        const float4* s4 = (const float4*)src;
        float4* st = (float4*)s_tgt;
        float4* ss = (float4*)s_src;
#pragma unroll
        for (int i = tid; i < (NPTS * 3) / 4; i += THREADS) {
            st[i] = t4[i];
            ss[i] = s4[i];
        }
    }
    __syncthreads();

    const int qi  = blockIdx.x * QPB + (tid >> 2);   // query index
    const int par = tid & 3;                         // which quarter of points

    // Build query point (jittered tgt for qi < NPTS*UPR, else src point).
    float qx, qy, qz;
    if (qi < NPTS * UPR) {
        int m = qi / UPR;
        int b = 3 * m;
        int nb = 3 * qi;     // qi == m*UPR + u -> noise linear index
        qx = fmaf(noise[nb + 0], 0.05f, s_tgt[b + 0]);
        qy = fmaf(noise[nb + 1], 0.05f, s_tgt[b + 1]);
        qz = fmaf(noise[nb + 2], 0.05f, s_tgt[b + 2]);
    } else {
        int b = 3 * (qi - NPTS * UPR);
        qx = s_src[b + 0];
        qy = s_src[b + 1];
        qz = s_src[b + 2];
    }

    // Private top-5 per cloud.
    float dT[KNN], dS[KNN];
    int   iT[KNN], iS[KNN];
#pragma unroll
    for (int k = 0; k < KNN; ++k) { dT[k] = 3.0e38f; dS[k] = 3.0e38f; iT[k] = 0; iS[k] = 0; }

    // Scan: this thread handles points j = 4*jj + par (interleaved -> conflict-free).
#pragma unroll 4
    for (int jj = 0; jj < NPTS / SPLIT; ++jj) {
        int j = (jj << 2) + par;
        int b = 3 * j;
        float tx = s_tgt[b], ty = s_tgt[b + 1], tz = s_tgt[b + 2];
        float dx = qx - tx, dy = qy - ty, dz = qz - tz;
        float d  = fmaf(dx, dx, fmaf(dy, dy, dz * dz));
        ins5(d, j, dT, iT);

        float sx = s_src[b], sy = s_src[b + 1], sz = s_src[b + 2];
        dx = qx - sx; dy = qy - sy; dz = qz - sz;
        d  = fmaf(dx, dx, fmaf(dy, dy, dz * dz));
        ins5(d, j, dS, iS);
    }

    // Merge the 4 partial top-5 lists within each 4-thread group.
    merge5(1, dT, iT);
    merge5(2, dT, iT);
    merge5(1, dS, iS);
    merge5(2, dS, iS);

    // Leader thread of each group computes the query's contribution.
    float contrib = 0.f;
    if (par == 0) {
        float gTx, gTy, gTz, uT;
        float gSx, gSy, gSz, uS;
        udf_from_knn(qx, qy, qz, dT, iT, s_tgt, gTx, gTy, gTz, uT);
        udf_from_knn(qx, qy, qz, dS, iS, s_src, gSx, gSy, gSz, uS);
        float e1 = fabsf(uT - uS);
        float e2 = fabsf(gSx - gTx) + fabsf(gSy - gTy) + fabsf(gSz - gTz);
        float t  = e1 + e2;
        contrib  = t * __expf(-BETA * t);
    }

    // Block reduction (deterministic per-block; smem reused after sync).
#pragma unroll
    for (int o = 16; o > 0; o >>= 1)
        contrib += __shfl_down_sync(0xFFFFFFFFu, contrib, o);

    __syncthreads();   // all smem reads (knn fetch) done before reuse
    if ((tid & 31) == 0) s_tgt[tid >> 5] = contrib;
    __syncthreads();
    if (tid == 0) {
        float s = 0.f;
#pragma unroll
        for (int w = 0; w < THREADS / 32; ++w) s += s_tgt[w];
        g_partial[blockIdx.x] = s;
    }
}

__global__ void dirdist_reduce(float* __restrict__ out)
{
    __shared__ float sh[8];
    int tid = threadIdx.x;
    float v = 0.f;
    for (int i = tid; i < NBLOCKS; i += 256) v += g_partial[i];
#pragma unroll
    for (int o = 16; o > 0; o >>= 1) v += __shfl_down_sync(0xFFFFFFFFu, v, o);
    if ((tid & 31) == 0) sh[tid >> 5] = v;
    __syncthreads();
    if (tid == 0) {
        float s = 0.f;
#pragma unroll
        for (int w = 0; w < 8; ++w) s += sh[w];
        out[0] = s * (1.0f / (float)QTOT);
    }
}

extern "C" void kernel_launch(void* const* d_in, const int* in_sizes, int n_in,
                              void* d_out, int out_size)
{
    const float* src   = (const float*)d_in[0];   // [1,2048,3]
    const float* tgt   = (const float*)d_in[1];   // [1,2048,3]
    const float* noise = (const float*)d_in[2];   // [1,2048,10,3]
    (void)in_sizes; (void)n_in; (void)out_size;

    dirdist_kernel<<<NBLOCKS, THREADS>>>(src, tgt, noise);
    dirdist_reduce<<<1, 256>>>((float*)d_out);
}